// round 1
// baseline (speedup 1.0000x reference)
#include <cuda_runtime.h>
#include <math.h>

#define NPTS 16384
#define MC   4096
#define DIMF 128
#define NH   4
#define DH   32
#define KNB  32
#define HID  512
#define RAD  0.3f
#define CAP  512
#define CPB  4

// ---------------- scratch (device globals; no allocation) ----------------
__device__ int   g_idxc[MC];
__device__ float g_xx[NPTS];
__device__ float g_Qp[NPTS*DIMF];
__device__ float g_Kp[NPTS*DIMF];
__device__ float g_Vp[NPTS*DIMF];
__device__ int   g_nbr[MC*KNB];
__device__ int   g_cnt[MC];
__device__ int   g_near[NPTS];
__device__ float g_ao[MC*DIMF];
__device__ float g_upd[MC*DIMF];
__device__ float g_c1[MC*DIMF];
__device__ float g_hid[MC*HID];
__device__ float g_ffn[MC*DIMF];
__device__ float g_c2[MC*DIMF];

// ---------------- idx_center dtype detection + convert ----------------
// JAX may silently emit int32 even though the reference asks for int64.
// Detect by checking whether the int64 interpretation of the first half
// (stays in-bounds for both layouts) is plausible.
__global__ void k_cvt_idx(const long long* __restrict__ raw) {
    __shared__ int s_ok;
    if (threadIdx.x == 0) s_ok = 1;
    __syncthreads();
    for (int m = threadIdx.x; m < MC/2; m += 256) {
        long long v = raw[m];
        if (v < 0 || v >= NPTS) s_ok = 0;  // benign race, only writes 0
    }
    __syncthreads();
    if (s_ok) {
        for (int m = threadIdx.x; m < MC; m += 256)
            g_idxc[m] = (int)raw[m];
    } else {
        const int* r32 = (const int*)raw;
        for (int m = threadIdx.x; m < MC; m += 256)
            g_idxc[m] = r32[m];
    }
}

// ---------------- |x|^2 per point ----------------
__global__ void k_xx(const float* __restrict__ xyz) {
    int n = blockIdx.x * 256 + threadIdx.x;
    float x = xyz[3*n], y = xyz[3*n+1], z = xyz[3*n+2];
    g_xx[n] = x*x + y*y + z*z;
}

// ---------------- per-center radius filter + exact top-K by rank ----------------
__global__ void k_topk(const float* __restrict__ xyz) {
    __shared__ float cd[CPB][CAP];
    __shared__ int   ci[CPB][CAP];
    __shared__ int   s_cnt[CPB];
    const int tid = threadIdx.x;
    const int m0 = blockIdx.x * CPB;
    if (tid < CPB) s_cnt[tid] = 0;
    __syncthreads();

    float cx[CPB], cy[CPB], cz[CPB], cc[CPB];
    #pragma unroll
    for (int g = 0; g < CPB; g++) {
        int ic = g_idxc[m0 + g];
        cx[g] = xyz[3*ic]; cy[g] = xyz[3*ic+1]; cz[g] = xyz[3*ic+2];
        cc[g] = cx[g]*cx[g] + cy[g]*cy[g] + cz[g]*cz[g];
    }

    for (int n = tid; n < NPTS; n += 256) {
        float x = xyz[3*n], y = xyz[3*n+1], z = xyz[3*n+2];
        float xn = g_xx[n];
        #pragma unroll
        for (int g = 0; g < CPB; g++) {
            float d2 = cc[g] + xn - 2.f*(cx[g]*x + cy[g]*y + cz[g]*z);
            float dist = sqrtf(fmaxf(d2, 1e-12f));
            if (dist < RAD) {
                int p = atomicAdd(&s_cnt[g], 1);
                if (p < CAP) { cd[g][p] = dist; ci[g][p] = n; }
            }
        }
    }
    __syncthreads();

    #pragma unroll
    for (int g = 0; g < CPB; g++) {
        int cnt = min(s_cnt[g], CAP);   // CAP=512 >> max possible (~170) for this density
        int m = m0 + g;
        for (int c = tid; c < cnt; c += 256) {
            float d = cd[g][c]; int i = ci[g][c];
            int rank = 0;
            for (int j = 0; j < cnt; j++) {
                float dj = cd[g][j];
                rank += (dj < d) || (dj == d && ci[g][j] < i);
            }
            if (rank < KNB) g_nbr[m*KNB + rank] = i;
        }
        int v = min(cnt, KNB);
        if (tid == 0) g_cnt[m] = v;
        if (tid >= v && tid < KNB) g_nbr[m*KNB + tid] = 0;
    }
}

// ---------------- per-point nearest center (argmin, first index on ties) -------
#define NCHUNK 2048
__global__ void k_nearest(const float* __restrict__ xyz) {
    __shared__ float4 sc[NCHUNK];
    const int n = blockIdx.x * 256 + threadIdx.x;
    const float x = xyz[3*n], y = xyz[3*n+1], z = xyz[3*n+2];
    const float xn = x*x + y*y + z*z;
    float best = 3.4e38f; int bi = 0;
    for (int base = 0; base < MC; base += NCHUNK) {
        __syncthreads();
        for (int j = threadIdx.x; j < NCHUNK; j += 256) {
            int ic = g_idxc[base + j];
            float a = xyz[3*ic], b = xyz[3*ic+1], c = xyz[3*ic+2];
            sc[j] = make_float4(a, b, c, a*a + b*b + c*c);
        }
        __syncthreads();
        #pragma unroll 4
        for (int j = 0; j < NCHUNK; j++) {
            float4 c = sc[j];
            float d2 = c.w + xn - 2.f*(c.x*x + c.y*y + c.z*z);
            d2 = fmaxf(d2, 1e-12f);
            if (d2 < best) { best = d2; bi = base + j; }
        }
    }
    g_near[n] = bi;
}

// ---------------- fp32 register-tiled GEMM: C = A @ W^T (+bias)(+relu) --------
// A: R x Cin, W: Cout x Cin (row major), C: R x Cout. All dims multiples of tile.
template<int BM, int BN>
__global__ __launch_bounds__(256, 2) void k_gemm(
    const float* __restrict__ A, const float* __restrict__ W,
    const float* __restrict__ bias, float* __restrict__ C,
    int Cin, int Cout, int relu)
{
    constexpr int BK = 16;
    constexpr int TM = BM / 16, TN = BN / 16;
    __shared__ float As[BK][BM + 4];
    __shared__ float Ws[BK][BN + 4];
    const int tid = threadIdx.x;
    const int tc = tid & 15, tr = tid >> 4;
    const int rowBase = blockIdx.x * BM;
    const int colBase = blockIdx.y * BN;

    float acc[TM][TN];
    #pragma unroll
    for (int i = 0; i < TM; i++)
        #pragma unroll
        for (int j = 0; j < TN; j++) acc[i][j] = 0.f;

    for (int k0 = 0; k0 < Cin; k0 += BK) {
        #pragma unroll
        for (int f = tid; f < BM * (BK/4); f += 256) {
            int row = f >> 2, kq = f & 3;
            float4 v = *reinterpret_cast<const float4*>(A + (size_t)(rowBase + row)*Cin + k0 + kq*4);
            As[kq*4+0][row] = v.x; As[kq*4+1][row] = v.y;
            As[kq*4+2][row] = v.z; As[kq*4+3][row] = v.w;
        }
        #pragma unroll
        for (int f = tid; f < BN * (BK/4); f += 256) {
            int col = f >> 2, kq = f & 3;
            float4 v = *reinterpret_cast<const float4*>(W + (size_t)(colBase + col)*Cin + k0 + kq*4);
            Ws[kq*4+0][col] = v.x; Ws[kq*4+1][col] = v.y;
            Ws[kq*4+2][col] = v.z; Ws[kq*4+3][col] = v.w;
        }
        __syncthreads();
        #pragma unroll
        for (int k = 0; k < BK; k++) {
            float a[TM], w[TN];
            #pragma unroll
            for (int i = 0; i < TM; i += 4)
                *reinterpret_cast<float4*>(&a[i]) = *reinterpret_cast<const float4*>(&As[k][tr*TM + i]);
            #pragma unroll
            for (int j = 0; j < TN; j += 4)
                *reinterpret_cast<float4*>(&w[j]) = *reinterpret_cast<const float4*>(&Ws[k][tc*TN + j]);
            #pragma unroll
            for (int i = 0; i < TM; i++)
                #pragma unroll
                for (int j = 0; j < TN; j++) acc[i][j] += a[i] * w[j];
        }
        __syncthreads();
    }

    #pragma unroll
    for (int i = 0; i < TM; i++) {
        int r = rowBase + tr*TM + i;
        #pragma unroll
        for (int j = 0; j < TN; j += 4) {
            int c = colBase + tc*TN + j;
            float4 o;
            o.x = acc[i][j+0]; o.y = acc[i][j+1]; o.z = acc[i][j+2]; o.w = acc[i][j+3];
            if (bias) { o.x += bias[c]; o.y += bias[c+1]; o.z += bias[c+2]; o.w += bias[c+3]; }
            if (relu) {
                o.x = fmaxf(o.x, 0.f); o.y = fmaxf(o.y, 0.f);
                o.z = fmaxf(o.z, 0.f); o.w = fmaxf(o.w, 0.f);
            }
            *reinterpret_cast<float4*>(C + (size_t)r*Cout + c) = o;
        }
    }
}

// ---------------- per-center attention over K=32 neighbors ----------------
__global__ void k_attn() {
    __shared__ float q[DIMF];
    __shared__ float kv[KNB][DIMF + 4];
    __shared__ float at[NH][KNB];
    __shared__ int nbr_s[KNB];
    __shared__ int s_cnt;
    const int m = blockIdx.x, tid = threadIdx.x;
    if (tid < KNB) nbr_s[tid] = g_nbr[m*KNB + tid];
    if (tid == 0) s_cnt = g_cnt[m];
    int ic = g_idxc[m];
    q[tid] = g_Qp[(size_t)ic*DIMF + tid] * 0.17677669529663687f;  // DH^-0.5
    __syncthreads();

    // stage K rows (coalesced float4)
    #pragma unroll
    for (int f = tid; f < KNB * (DIMF/4); f += 128) {
        int s = f >> 5, c4 = f & 31;
        *reinterpret_cast<float4*>(&kv[s][c4*4]) =
            *reinterpret_cast<const float4*>(&g_Kp[(size_t)nbr_s[s]*DIMF + c4*4]);
    }
    __syncthreads();

    const int h = tid >> 5, lane = tid & 31;
    const int cnt = s_cnt;
    float logit = -1e9f;
    if (lane < cnt) {
        float a = 0.f;
        #pragma unroll
        for (int d = 0; d < DH; d++) a += q[h*DH + d] * kv[lane][h*DH + d];
        logit = a;
    }
    float mx = logit;
    #pragma unroll
    for (int o = 16; o > 0; o >>= 1) mx = fmaxf(mx, __shfl_xor_sync(0xffffffffu, mx, o));
    float e = (lane < cnt) ? expf(logit - mx) : 0.f;
    float sm = e;
    #pragma unroll
    for (int o = 16; o > 0; o >>= 1) sm += __shfl_xor_sync(0xffffffffu, sm, o);
    at[h][lane] = e / sm;
    __syncthreads();

    // stage V rows (reuse buffer)
    #pragma unroll
    for (int f = tid; f < KNB * (DIMF/4); f += 128) {
        int s = f >> 5, c4 = f & 31;
        *reinterpret_cast<float4*>(&kv[s][c4*4]) =
            *reinterpret_cast<const float4*>(&g_Vp[(size_t)nbr_s[s]*DIMF + c4*4]);
    }
    __syncthreads();

    float acc = 0.f;
    #pragma unroll
    for (int kk = 0; kk < KNB; kk++) acc += at[h][kk] * kv[kk][h*DH + lane];
    // out.transpose(0,2,1).reshape -> column = d*H + h
    g_ao[(size_t)m*DIMF + lane*NH + h] = acc;
}

// ---------------- LayerNorm + residual ----------------
__global__ void k_ln_res(const float* __restrict__ x,
                         const float* __restrict__ resid,
                         const float* __restrict__ g,
                         const float* __restrict__ b,
                         float* __restrict__ out,
                         int gatherResid)
{
    const int m = blockIdx.x, tid = threadIdx.x;
    __shared__ float red[4];
    float v = x[(size_t)m*DIMF + tid];
    float s = v;
    #pragma unroll
    for (int o = 16; o > 0; o >>= 1) s += __shfl_xor_sync(0xffffffffu, s, o);
    if ((tid & 31) == 0) red[tid >> 5] = s;
    __syncthreads();
    float mu = (red[0] + red[1] + red[2] + red[3]) * (1.f/DIMF);
    __syncthreads();
    float dv = v - mu;
    float s2 = dv * dv;
    #pragma unroll
    for (int o = 16; o > 0; o >>= 1) s2 += __shfl_xor_sync(0xffffffffu, s2, o);
    if ((tid & 31) == 0) red[tid >> 5] = s2;
    __syncthreads();
    float var = (red[0] + red[1] + red[2] + red[3]) * (1.f/DIMF);
    float ln = dv * rsqrtf(var + 1e-5f) * g[tid] + b[tid];
    int rrow = gatherResid ? g_idxc[m] : m;
    out[(size_t)m*DIMF + tid] = resid[(size_t)rrow*DIMF + tid] + ln;
}

// ---------------- final scatter: out = feats + c2[nearest] ----------------
__global__ void k_scatter(const float* __restrict__ feats, float* __restrict__ out) {
    int i = blockIdx.x * 256 + threadIdx.x;   // float4 index
    int n = i >> 5, c4 = i & 31;
    int ctr = g_near[n];
    float4 f = *reinterpret_cast<const float4*>(feats + (size_t)n*DIMF + c4*4);
    float4 c = *reinterpret_cast<const float4*>(g_c2 + (size_t)ctr*DIMF + c4*4);
    f.x += c.x; f.y += c.y; f.z += c.z; f.w += c.w;
    *reinterpret_cast<float4*>(out + (size_t)n*DIMF + c4*4) = f;
}

// ---------------- launch ----------------
extern "C" void kernel_launch(void* const* d_in, const int* in_sizes, int n_in,
                              void* d_out, int out_size) {
    const float* xyz   = (const float*)d_in[0];
    const float* feats = (const float*)d_in[1];
    const long long* idxc = (const long long*)d_in[2];
    const float* Wq = (const float*)d_in[3];
    const float* Wk = (const float*)d_in[4];
    const float* Wv = (const float*)d_in[5];
    const float* Wo = (const float*)d_in[6];
    const float* bo = (const float*)d_in[7];
    const float* g1 = (const float*)d_in[8];
    const float* be1 = (const float*)d_in[9];
    const float* g2 = (const float*)d_in[10];
    const float* be2 = (const float*)d_in[11];
    const float* W1 = (const float*)d_in[12];
    const float* b1f = (const float*)d_in[13];
    const float* W2 = (const float*)d_in[14];
    const float* b2f = (const float*)d_in[15];
    float* out = (float*)d_out;

    float *qp, *kp, *vp, *ao, *upd, *c1, *hid, *ffn;
    cudaGetSymbolAddress((void**)&qp,  g_Qp);
    cudaGetSymbolAddress((void**)&kp,  g_Kp);
    cudaGetSymbolAddress((void**)&vp,  g_Vp);
    cudaGetSymbolAddress((void**)&ao,  g_ao);
    cudaGetSymbolAddress((void**)&upd, g_upd);
    cudaGetSymbolAddress((void**)&c1,  g_c1);
    cudaGetSymbolAddress((void**)&hid, g_hid);
    cudaGetSymbolAddress((void**)&ffn, g_ffn);
    float *c2;
    cudaGetSymbolAddress((void**)&c2,  g_c2);

    k_cvt_idx<<<1, 256>>>(idxc);
    k_xx<<<NPTS/256, 256>>>(xyz);
    k_topk<<<MC/CPB, 256>>>(xyz);
    k_nearest<<<NPTS/256, 256>>>(xyz);

    // point-wise projections (8x less work than per-neighbor projection)
    k_gemm<128,128><<<dim3(NPTS/128, 1), 256>>>(feats, Wq, nullptr, qp, DIMF, DIMF, 0);
    k_gemm<128,128><<<dim3(NPTS/128, 1), 256>>>(feats, Wk, nullptr, kp, DIMF, DIMF, 0);
    k_gemm<128,128><<<dim3(NPTS/128, 1), 256>>>(feats, Wv, nullptr, vp, DIMF, DIMF, 0);

    k_attn<<<MC, 128>>>();

    k_gemm<64,64><<<dim3(MC/64, DIMF/64), 256>>>(ao, Wo, bo, upd, DIMF, DIMF, 0);
    k_ln_res<<<MC, DIMF>>>(upd, feats, g1, be1, c1, 1);
    k_gemm<128,128><<<dim3(MC/128, HID/128), 256>>>(c1, W1, b1f, hid, DIMF, HID, 1);
    k_gemm<64,64><<<dim3(MC/64, DIMF/64), 256>>>(hid, W2, b2f, ffn, HID, DIMF, 0);
    k_ln_res<<<MC, DIMF>>>(ffn, c1, g2, be2, c2, 0);

    k_scatter<<<NPTS*(DIMF/4)/256, 256>>>(feats, out);
}

// round 2
// speedup vs baseline: 1.1194x; 1.1194x over previous
#include <cuda_runtime.h>
#include <math.h>

#define NPTS 16384
#define MC   4096
#define DIMF 128
#define NH   4
#define DH   32
#define KNB  32
#define HID  512
#define RAD  0.3f
#define CAP  512
#define CPB  8
#define CCH  512   // centers per k_nearest block

// ---------------- scratch (device globals; no allocation) ----------------
__device__ int   g_idxc[MC];
__device__ float g_xx[NPTS];
__device__ float g_Qp[NPTS*DIMF];
__device__ float g_Kp[NPTS*DIMF];
__device__ float g_Vp[NPTS*DIMF];
__device__ int   g_nbr[MC*KNB];
__device__ int   g_cnt[MC];
__device__ unsigned long long g_nearKey[NPTS];
__device__ float g_ao[MC*DIMF];
__device__ float g_upd[MC*DIMF];
__device__ float g_c1[MC*DIMF];
__device__ float g_hid[MC*HID];
__device__ float g_ffn[MC*DIMF];
__device__ float g_c2[MC*DIMF];

// ---------------- idx_center dtype detection + convert + init ----------------
__global__ void k_cvt_idx(const long long* __restrict__ raw) {
    __shared__ int s_ok;
    if (threadIdx.x == 0) s_ok = 1;
    __syncthreads();
    for (int m = threadIdx.x; m < MC/2; m += 256) {
        long long v = raw[m];
        if (v < 0 || v >= NPTS) s_ok = 0;  // benign race, only writes 0
    }
    __syncthreads();
    if (s_ok) {
        for (int m = threadIdx.x; m < MC; m += 256)
            g_idxc[m] = (int)raw[m];
    } else {
        const int* r32 = (const int*)raw;
        for (int m = threadIdx.x; m < MC; m += 256)
            g_idxc[m] = r32[m];
    }
}

// |x|^2 per point + init nearest keys
__global__ void k_xx(const float* __restrict__ xyz) {
    int n = blockIdx.x * 256 + threadIdx.x;
    float x = xyz[3*n], y = xyz[3*n+1], z = xyz[3*n+2];
    g_xx[n] = x*x + y*y + z*z;
    g_nearKey[n] = ~0ull;
}

// ---------------- per-center radius filter + exact top-K by rank ----------------
__global__ __launch_bounds__(256) void k_topk(const float* __restrict__ xyz) {
    __shared__ float cd[CPB][CAP];
    __shared__ int   ci[CPB][CAP];
    __shared__ int   s_cnt[CPB];
    const int tid = threadIdx.x;
    const int m0 = blockIdx.x * CPB;
    if (tid < CPB) s_cnt[tid] = 0;
    __syncthreads();

    float cx[CPB], cy[CPB], cz[CPB], cc[CPB];
    #pragma unroll
    for (int g = 0; g < CPB; g++) {
        int ic = g_idxc[m0 + g];
        cx[g] = xyz[3*ic]; cy[g] = xyz[3*ic+1]; cz[g] = xyz[3*ic+2];
        cc[g] = cx[g]*cx[g] + cy[g]*cy[g] + cz[g]*cz[g];
    }

    for (int n = tid; n < NPTS; n += 256) {
        float x = xyz[3*n], y = xyz[3*n+1], z = xyz[3*n+2];
        float xn = g_xx[n];
        #pragma unroll
        for (int g = 0; g < CPB; g++) {
            float d2 = cc[g] + xn - 2.f*(cx[g]*x + cy[g]*y + cz[g]*z);
            float dist = sqrtf(fmaxf(d2, 1e-12f));
            if (dist < RAD) {
                int p = atomicAdd(&s_cnt[g], 1);
                if (p < CAP) { cd[g][p] = dist; ci[g][p] = n; }
            }
        }
    }
    __syncthreads();

    #pragma unroll
    for (int g = 0; g < CPB; g++) {
        int cnt = min(s_cnt[g], CAP);
        int m = m0 + g;
        for (int c = tid; c < cnt; c += 256) {
            float d = cd[g][c]; int i = ci[g][c];
            int rank = 0;
            for (int j = 0; j < cnt; j++) {
                float dj = cd[g][j];
                rank += (dj < d) || (dj == d && ci[g][j] < i);
            }
            if (rank < KNB) g_nbr[m*KNB + rank] = i;
        }
        int v = min(cnt, KNB);
        if (tid == 0) g_cnt[m] = v;
        if (tid >= v && tid < KNB) g_nbr[m*KNB + tid] = 0;
    }
}

// ---------------- per-point nearest center: chunked + packed atomicMin --------
// key = (float_bits(d2) << 32) | center_idx  ->  global min == argmin with
// first-index tie-break (d2 >= 0 so float bits are order-preserving).
__global__ __launch_bounds__(256) void k_nearest(const float* __restrict__ xyz) {
    __shared__ float4 sc[CCH];
    const int n = blockIdx.x * 256 + threadIdx.x;
    const int base = blockIdx.y * CCH;
    for (int j = threadIdx.x; j < CCH; j += 256) {
        int ic = g_idxc[base + j];
        float a = xyz[3*ic], b = xyz[3*ic+1], c = xyz[3*ic+2];
        sc[j] = make_float4(a, b, c, a*a + b*b + c*c);
    }
    const float x = xyz[3*n], y = xyz[3*n+1], z = xyz[3*n+2];
    const float xn = x*x + y*y + z*z;
    __syncthreads();
    float best = 3.4e38f; int bi = 0;
    #pragma unroll 4
    for (int j = 0; j < CCH; j++) {
        float4 c = sc[j];
        float d2 = c.w + xn - 2.f*(c.x*x + c.y*y + c.z*z);
        d2 = fmaxf(d2, 1e-12f);
        if (d2 < best) { best = d2; bi = j; }
    }
    unsigned long long key =
        ((unsigned long long)__float_as_uint(best) << 32) | (unsigned)(base + bi);
    atomicMin(&g_nearKey[n], key);
}

// ---------------- fp32 register-tiled GEMM: C = A @ W^T (+bias)(+relu) --------
template<int BM, int BN>
__device__ __forceinline__ void gemm_body(
    const float* __restrict__ A, const float* __restrict__ W,
    const float* __restrict__ bias, float* __restrict__ C,
    int Cin, int Cout, int relu)
{
    constexpr int BK = 16;
    constexpr int TM = BM / 16, TN = BN / 16;
    __shared__ float As[BK][BM + 4];
    __shared__ float Ws[BK][BN + 4];
    const int tid = threadIdx.x;
    const int tc = tid & 15, tr = tid >> 4;
    const int rowBase = blockIdx.x * BM;
    const int colBase = blockIdx.y * BN;

    float acc[TM][TN];
    #pragma unroll
    for (int i = 0; i < TM; i++)
        #pragma unroll
        for (int j = 0; j < TN; j++) acc[i][j] = 0.f;

    for (int k0 = 0; k0 < Cin; k0 += BK) {
        #pragma unroll
        for (int f = tid; f < BM * (BK/4); f += 256) {
            int row = f >> 2, kq = f & 3;
            float4 v = *reinterpret_cast<const float4*>(A + (size_t)(rowBase + row)*Cin + k0 + kq*4);
            As[kq*4+0][row] = v.x; As[kq*4+1][row] = v.y;
            As[kq*4+2][row] = v.z; As[kq*4+3][row] = v.w;
        }
        #pragma unroll
        for (int f = tid; f < BN * (BK/4); f += 256) {
            int col = f >> 2, kq = f & 3;
            float4 v = *reinterpret_cast<const float4*>(W + (size_t)(colBase + col)*Cin + k0 + kq*4);
            Ws[kq*4+0][col] = v.x; Ws[kq*4+1][col] = v.y;
            Ws[kq*4+2][col] = v.z; Ws[kq*4+3][col] = v.w;
        }
        __syncthreads();
        #pragma unroll
        for (int k = 0; k < BK; k++) {
            float a[TM], w[TN];
            #pragma unroll
            for (int i = 0; i < TM; i += 4)
                *reinterpret_cast<float4*>(&a[i]) = *reinterpret_cast<const float4*>(&As[k][tr*TM + i]);
            #pragma unroll
            for (int j = 0; j < TN; j += 4)
                *reinterpret_cast<float4*>(&w[j]) = *reinterpret_cast<const float4*>(&Ws[k][tc*TN + j]);
            #pragma unroll
            for (int i = 0; i < TM; i++)
                #pragma unroll
                for (int j = 0; j < TN; j++) acc[i][j] += a[i] * w[j];
        }
        __syncthreads();
    }

    #pragma unroll
    for (int i = 0; i < TM; i++) {
        int r = rowBase + tr*TM + i;
        #pragma unroll
        for (int j = 0; j < TN; j += 4) {
            int c = colBase + tc*TN + j;
            float4 o;
            o.x = acc[i][j+0]; o.y = acc[i][j+1]; o.z = acc[i][j+2]; o.w = acc[i][j+3];
            if (bias) { o.x += bias[c]; o.y += bias[c+1]; o.z += bias[c+2]; o.w += bias[c+3]; }
            if (relu) {
                o.x = fmaxf(o.x, 0.f); o.y = fmaxf(o.y, 0.f);
                o.z = fmaxf(o.z, 0.f); o.w = fmaxf(o.w, 0.f);
            }
            *reinterpret_cast<float4*>(C + (size_t)r*Cout + c) = o;
        }
    }
}

template<int BM, int BN>
__global__ __launch_bounds__(256, 2) void k_gemm(
    const float* __restrict__ A, const float* __restrict__ W,
    const float* __restrict__ bias, float* __restrict__ C,
    int Cin, int Cout, int relu)
{
    gemm_body<BM, BN>(A, W, bias, C, Cin, Cout, relu);
}

// QKV fused: z selects weight/output; one launch, 3x blocks.
struct P3 { const float* W[3]; float* C[3]; };
__global__ __launch_bounds__(256, 2) void k_gemm_qkv(const float* __restrict__ A, P3 p)
{
    gemm_body<128, 128>(A, p.W[blockIdx.z], nullptr, p.C[blockIdx.z], DIMF, DIMF, 0);
}

// ---------------- per-center attention over K=32 neighbors ----------------
__global__ void k_attn() {
    __shared__ float q[DIMF];
    __shared__ float kv[KNB][DIMF + 4];
    __shared__ float at[NH][KNB];
    __shared__ int nbr_s[KNB];
    __shared__ int s_cnt;
    const int m = blockIdx.x, tid = threadIdx.x;
    if (tid < KNB) nbr_s[tid] = g_nbr[m*KNB + tid];
    if (tid == 0) s_cnt = g_cnt[m];
    int ic = g_idxc[m];
    q[tid] = g_Qp[(size_t)ic*DIMF + tid] * 0.17677669529663687f;  // DH^-0.5
    __syncthreads();

    #pragma unroll
    for (int f = tid; f < KNB * (DIMF/4); f += 128) {
        int s = f >> 5, c4 = f & 31;
        *reinterpret_cast<float4*>(&kv[s][c4*4]) =
            *reinterpret_cast<const float4*>(&g_Kp[(size_t)nbr_s[s]*DIMF + c4*4]);
    }
    __syncthreads();

    const int h = tid >> 5, lane = tid & 31;
    const int cnt = s_cnt;
    float logit = -1e9f;
    if (lane < cnt) {
        float a = 0.f;
        #pragma unroll
        for (int d = 0; d < DH; d++) a += q[h*DH + d] * kv[lane][h*DH + d];
        logit = a;
    }
    float mx = logit;
    #pragma unroll
    for (int o = 16; o > 0; o >>= 1) mx = fmaxf(mx, __shfl_xor_sync(0xffffffffu, mx, o));
    float e = (lane < cnt) ? expf(logit - mx) : 0.f;
    float sm = e;
    #pragma unroll
    for (int o = 16; o > 0; o >>= 1) sm += __shfl_xor_sync(0xffffffffu, sm, o);
    at[h][lane] = e / sm;
    __syncthreads();

    #pragma unroll
    for (int f = tid; f < KNB * (DIMF/4); f += 128) {
        int s = f >> 5, c4 = f & 31;
        *reinterpret_cast<float4*>(&kv[s][c4*4]) =
            *reinterpret_cast<const float4*>(&g_Vp[(size_t)nbr_s[s]*DIMF + c4*4]);
    }
    __syncthreads();

    float acc = 0.f;
    #pragma unroll
    for (int kk = 0; kk < KNB; kk++) acc += at[h][kk] * kv[kk][h*DH + lane];
    g_ao[(size_t)m*DIMF + lane*NH + h] = acc;   // transpose(0,2,1) layout
}

// ---------------- LayerNorm + residual ----------------
__global__ void k_ln_res(const float* __restrict__ x,
                         const float* __restrict__ resid,
                         const float* __restrict__ g,
                         const float* __restrict__ b,
                         float* __restrict__ out,
                         int gatherResid)
{
    const int m = blockIdx.x, tid = threadIdx.x;
    __shared__ float red[4];
    float v = x[(size_t)m*DIMF + tid];
    float s = v;
    #pragma unroll
    for (int o = 16; o > 0; o >>= 1) s += __shfl_xor_sync(0xffffffffu, s, o);
    if ((tid & 31) == 0) red[tid >> 5] = s;
    __syncthreads();
    float mu = (red[0] + red[1] + red[2] + red[3]) * (1.f/DIMF);
    __syncthreads();
    float dv = v - mu;
    float s2 = dv * dv;
    #pragma unroll
    for (int o = 16; o > 0; o >>= 1) s2 += __shfl_xor_sync(0xffffffffu, s2, o);
    if ((tid & 31) == 0) red[tid >> 5] = s2;
    __syncthreads();
    float var = (red[0] + red[1] + red[2] + red[3]) * (1.f/DIMF);
    float ln = dv * rsqrtf(var + 1e-5f) * g[tid] + b[tid];
    int rrow = gatherResid ? g_idxc[m] : m;
    out[(size_t)m*DIMF + tid] = resid[(size_t)rrow*DIMF + tid] + ln;
}

// ---------------- final scatter: out = feats + c2[nearest] ----------------
__global__ void k_scatter(const float* __restrict__ feats, float* __restrict__ out) {
    int i = blockIdx.x * 256 + threadIdx.x;   // float4 index
    int n = i >> 5, c4 = i & 31;
    int ctr = (int)(g_nearKey[n] & 0xffffffffu);
    float4 f = *reinterpret_cast<const float4*>(feats + (size_t)n*DIMF + c4*4);
    float4 c = *reinterpret_cast<const float4*>(g_c2 + (size_t)ctr*DIMF + c4*4);
    f.x += c.x; f.y += c.y; f.z += c.z; f.w += c.w;
    *reinterpret_cast<float4*>(out + (size_t)n*DIMF + c4*4) = f;
}

// ---------------- launch ----------------
extern "C" void kernel_launch(void* const* d_in, const int* in_sizes, int n_in,
                              void* d_out, int out_size) {
    const float* xyz   = (const float*)d_in[0];
    const float* feats = (const float*)d_in[1];
    const long long* idxc = (const long long*)d_in[2];
    const float* Wq = (const float*)d_in[3];
    const float* Wk = (const float*)d_in[4];
    const float* Wv = (const float*)d_in[5];
    const float* Wo = (const float*)d_in[6];
    const float* bo = (const float*)d_in[7];
    const float* g1 = (const float*)d_in[8];
    const float* be1 = (const float*)d_in[9];
    const float* g2 = (const float*)d_in[10];
    const float* be2 = (const float*)d_in[11];
    const float* W1 = (const float*)d_in[12];
    const float* b1f = (const float*)d_in[13];
    const float* W2 = (const float*)d_in[14];
    const float* b2f = (const float*)d_in[15];
    float* out = (float*)d_out;

    float *qp, *kp, *vp, *ao, *upd, *c1, *hid, *ffn, *c2;
    cudaGetSymbolAddress((void**)&qp,  g_Qp);
    cudaGetSymbolAddress((void**)&kp,  g_Kp);
    cudaGetSymbolAddress((void**)&vp,  g_Vp);
    cudaGetSymbolAddress((void**)&ao,  g_ao);
    cudaGetSymbolAddress((void**)&upd, g_upd);
    cudaGetSymbolAddress((void**)&c1,  g_c1);
    cudaGetSymbolAddress((void**)&hid, g_hid);
    cudaGetSymbolAddress((void**)&ffn, g_ffn);
    cudaGetSymbolAddress((void**)&c2,  g_c2);

    k_cvt_idx<<<1, 256>>>(idxc);
    k_xx<<<NPTS/256, 256>>>(xyz);
    k_topk<<<MC/CPB, 256>>>(xyz);
    k_nearest<<<dim3(NPTS/256, MC/CCH), 256>>>(xyz);

    P3 p;
    p.W[0] = Wq; p.W[1] = Wk; p.W[2] = Wv;
    p.C[0] = qp; p.C[1] = kp; p.C[2] = vp;
    k_gemm_qkv<<<dim3(NPTS/128, 1, 3), 256>>>(feats, p);

    k_attn<<<MC, 128>>>();

    k_gemm<64,64><<<dim3(MC/64, DIMF/64), 256>>>(ao, Wo, bo, upd, DIMF, DIMF, 0);
    k_ln_res<<<MC, DIMF>>>(upd, feats, g1, be1, c1, 1);
    k_gemm<64,128><<<dim3(MC/64, HID/128), 256>>>(c1, W1, b1f, hid, DIMF, HID, 1);
    k_gemm<64,64><<<dim3(MC/64, DIMF/64), 256>>>(hid, W2, b2f, ffn, HID, DIMF, 0);
    k_ln_res<<<MC, DIMF>>>(ffn, c1, g2, be2, c2, 0);

    k_scatter<<<NPTS*(DIMF/4)/256, 256>>>(feats, out);
}

// round 3
// speedup vs baseline: 1.5259x; 1.3632x over previous
#include <cuda_runtime.h>
#include <math.h>

#define NPTS 16384
#define MC   4096
#define DIMF 128
#define NH   4
#define DH   32
#define KNB  32
#define HID  512
#define RAD  0.3f
#define R2L  0.09000902f   // (RAD^2)*(1+1e-4): loose prefilter, exact test after
#define CAP  512
#define CPB  8
#define CCH  512   // centers per k_nearest block

// ---------------- scratch (device globals; no allocation) ----------------
__device__ int    g_idxc[MC];
__device__ float4 g_pts[NPTS];        // x,y,z,|x|^2
__device__ float  g_Qp[NPTS*DIMF];
__device__ float  g_Kp[NPTS*DIMF];
__device__ float  g_Vp[NPTS*DIMF];
__device__ int    g_nbr[MC*KNB];
__device__ int    g_cnt[MC];
__device__ unsigned long long g_nearKey[NPTS];
__device__ float  g_ao[MC*DIMF];
__device__ float  g_upd[MC*DIMF];
__device__ float  g_c1[MC*DIMF];
__device__ float  g_hid[MC*HID];
__device__ float  g_ffn[MC*DIMF];
__device__ float  g_c2[MC*DIMF];

// ---------------- idx_center dtype detection + convert ----------------
__global__ void k_cvt_idx(const long long* __restrict__ raw) {
    __shared__ int s_ok;
    if (threadIdx.x == 0) s_ok = 1;
    __syncthreads();
    for (int m = threadIdx.x; m < MC/2; m += 256) {
        long long v = raw[m];
        if (v < 0 || v >= NPTS) s_ok = 0;  // benign race, only writes 0
    }
    __syncthreads();
    if (s_ok) {
        for (int m = threadIdx.x; m < MC; m += 256)
            g_idxc[m] = (int)raw[m];
    } else {
        const int* r32 = (const int*)raw;
        for (int m = threadIdx.x; m < MC; m += 256)
            g_idxc[m] = r32[m];
    }
}

// pack points + init nearest keys
__global__ void k_xx(const float* __restrict__ xyz) {
    int n = blockIdx.x * 256 + threadIdx.x;
    float x = xyz[3*n], y = xyz[3*n+1], z = xyz[3*n+2];
    g_pts[n] = make_float4(x, y, z, x*x + y*y + z*z);
    g_nearKey[n] = ~0ull;
}

// ---------------- per-center radius filter + exact top-K by rank ----------------
// Prefilter with d2 (no sqrt); exact sqrt-based test + dist only for ~0.7% hits.
__global__ __launch_bounds__(256) void k_topk() {
    __shared__ float cd[CPB][CAP];
    __shared__ int   ci[CPB][CAP];
    __shared__ int   s_cnt[CPB];
    const int tid = threadIdx.x;
    const int m0 = blockIdx.x * CPB;
    if (tid < CPB) s_cnt[tid] = 0;
    __syncthreads();

    float cx2[CPB], cy2[CPB], cz2[CPB], cc[CPB];
    #pragma unroll
    for (int g = 0; g < CPB; g++) {
        float4 c = g_pts[g_idxc[m0 + g]];
        cx2[g] = -2.f*c.x; cy2[g] = -2.f*c.y; cz2[g] = -2.f*c.z; cc[g] = c.w;
    }
    __syncthreads();

    for (int n = tid; n < NPTS; n += 256) {
        float4 p = g_pts[n];
        float rhs = R2L - p.w;   // compare t < R2L - xn  (t = cc - 2*dot)
        #pragma unroll
        for (int g = 0; g < CPB; g++) {
            float t = fmaf(cx2[g], p.x, cc[g]);
            t = fmaf(cy2[g], p.y, t);
            t = fmaf(cz2[g], p.z, t);
            if (t < rhs) {
                float dist = sqrtf(fmaxf(t + p.w, 1e-12f));
                if (dist < RAD) {
                    int q = atomicAdd(&s_cnt[g], 1);
                    if (q < CAP) { cd[g][q] = dist; ci[g][q] = n; }
                }
            }
        }
    }
    __syncthreads();

    #pragma unroll
    for (int g = 0; g < CPB; g++) {
        int cnt = min(s_cnt[g], CAP);
        int m = m0 + g;
        for (int c = tid; c < cnt; c += 256) {
            float d = cd[g][c]; int i = ci[g][c];
            int rank = 0;
            for (int j = 0; j < cnt; j++) {
                float dj = cd[g][j];
                rank += (dj < d) || (dj == d && ci[g][j] < i);
            }
            if (rank < KNB) g_nbr[m*KNB + rank] = i;
        }
        int v = min(cnt, KNB);
        if (tid == 0) g_cnt[m] = v;
        if (tid >= v && tid < KNB) g_nbr[m*KNB + tid] = 0;
    }
}

// ---------------- per-point nearest center: 2 pts/thread + packed atomicMin ----
__global__ __launch_bounds__(256) void k_nearest() {
    __shared__ float4 sc[CCH];
    const int tid = threadIdx.x;
    const int n0 = blockIdx.x * 512 + tid;
    const int n1 = n0 + 256;
    const int base = blockIdx.y * CCH;
    for (int j = tid; j < CCH; j += 256)
        sc[j] = g_pts[g_idxc[base + j]];
    float4 p0 = g_pts[n0], p1 = g_pts[n1];
    __syncthreads();
    float b0 = 3.4e38f, b1 = 3.4e38f; int i0 = 0, i1 = 0;
    #pragma unroll 8
    for (int j = 0; j < CCH; j++) {
        float4 c = sc[j];
        float t0 = fmaf(c.x, p0.x, fmaf(c.y, p0.y, c.z*p0.z));
        float d0 = fmaf(-2.f, t0, c.w);          // = cc - 2*dot (xn added later)
        float t1 = fmaf(c.x, p1.x, fmaf(c.y, p1.y, c.z*p1.z));
        float d1 = fmaf(-2.f, t1, c.w);
        if (d0 < b0) { b0 = d0; i0 = j; }
        if (d1 < b1) { b1 = d1; i1 = j; }
    }
    float f0 = fmaxf(b0 + p0.w, 0.f);            // nonneg -> bit-order preserving
    float f1 = fmaxf(b1 + p1.w, 0.f);
    unsigned long long k0 =
        ((unsigned long long)__float_as_uint(f0) << 32) | (unsigned)(base + i0);
    unsigned long long k1 =
        ((unsigned long long)__float_as_uint(f1) << 32) | (unsigned)(base + i1);
    atomicMin(&g_nearKey[n0], k0);
    atomicMin(&g_nearKey[n1], k1);
}

// ---------------- fp32 register-tiled GEMM: C = A @ W^T (+bias)(+relu) --------
template<int BM, int BN>
__device__ __forceinline__ void gemm_body(
    const float* __restrict__ A, const float* __restrict__ W,
    const float* __restrict__ bias, float* __restrict__ C,
    int Cin, int Cout, int relu)
{
    constexpr int BK = 16;
    constexpr int TM = BM / 16, TN = BN / 16;
    __shared__ float As[BK][BM + 4];
    __shared__ float Ws[BK][BN + 4];
    const int tid = threadIdx.x;
    const int tc = tid & 15, tr = tid >> 4;
    const int rowBase = blockIdx.x * BM;
    const int colBase = blockIdx.y * BN;

    float acc[TM][TN];
    #pragma unroll
    for (int i = 0; i < TM; i++)
        #pragma unroll
        for (int j = 0; j < TN; j++) acc[i][j] = 0.f;

    for (int k0 = 0; k0 < Cin; k0 += BK) {
        #pragma unroll
        for (int f = tid; f < BM * (BK/4); f += 256) {
            int row = f >> 2, kq = f & 3;
            float4 v = *reinterpret_cast<const float4*>(A + (size_t)(rowBase + row)*Cin + k0 + kq*4);
            As[kq*4+0][row] = v.x; As[kq*4+1][row] = v.y;
            As[kq*4+2][row] = v.z; As[kq*4+3][row] = v.w;
        }
        #pragma unroll
        for (int f = tid; f < BN * (BK/4); f += 256) {
            int col = f >> 2, kq = f & 3;
            float4 v = *reinterpret_cast<const float4*>(W + (size_t)(colBase + col)*Cin + k0 + kq*4);
            Ws[kq*4+0][col] = v.x; Ws[kq*4+1][col] = v.y;
            Ws[kq*4+2][col] = v.z; Ws[kq*4+3][col] = v.w;
        }
        __syncthreads();
        #pragma unroll
        for (int k = 0; k < BK; k++) {
            float a[TM], w[TN];
            #pragma unroll
            for (int i = 0; i < TM; i += 4)
                *reinterpret_cast<float4*>(&a[i]) = *reinterpret_cast<const float4*>(&As[k][tr*TM + i]);
            #pragma unroll
            for (int j = 0; j < TN; j += 4)
                *reinterpret_cast<float4*>(&w[j]) = *reinterpret_cast<const float4*>(&Ws[k][tc*TN + j]);
            #pragma unroll
            for (int i = 0; i < TM; i++)
                #pragma unroll
                for (int j = 0; j < TN; j++) acc[i][j] += a[i] * w[j];
        }
        __syncthreads();
    }

    #pragma unroll
    for (int i = 0; i < TM; i++) {
        int r = rowBase + tr*TM + i;
        #pragma unroll
        for (int j = 0; j < TN; j += 4) {
            int c = colBase + tc*TN + j;
            float4 o;
            o.x = acc[i][j+0]; o.y = acc[i][j+1]; o.z = acc[i][j+2]; o.w = acc[i][j+3];
            if (bias) { o.x += bias[c]; o.y += bias[c+1]; o.z += bias[c+2]; o.w += bias[c+3]; }
            if (relu) {
                o.x = fmaxf(o.x, 0.f); o.y = fmaxf(o.y, 0.f);
                o.z = fmaxf(o.z, 0.f); o.w = fmaxf(o.w, 0.f);
            }
            *reinterpret_cast<float4*>(C + (size_t)r*Cout + c) = o;
        }
    }
}

template<int BM, int BN>
__global__ __launch_bounds__(256, 2) void k_gemm(
    const float* __restrict__ A, const float* __restrict__ W,
    const float* __restrict__ bias, float* __restrict__ C,
    int Cin, int Cout, int relu)
{
    gemm_body<BM, BN>(A, W, bias, C, Cin, Cout, relu);
}

struct P3 { const float* W[3]; float* C[3]; };
__global__ __launch_bounds__(256, 2) void k_gemm_qkv(const float* __restrict__ A, P3 p)
{
    gemm_body<128, 128>(A, p.W[blockIdx.z], nullptr, p.C[blockIdx.z], DIMF, DIMF, 0);
}

// ---------------- per-center attention over K=32 neighbors ----------------
__global__ void k_attn() {
    __shared__ float q[DIMF];
    __shared__ float kv[KNB][DIMF + 4];
    __shared__ float at[NH][KNB];
    __shared__ int nbr_s[KNB];
    __shared__ int s_cnt;
    const int m = blockIdx.x, tid = threadIdx.x;
    if (tid < KNB) nbr_s[tid] = g_nbr[m*KNB + tid];
    if (tid == 0) s_cnt = g_cnt[m];
    int ic = g_idxc[m];
    q[tid] = g_Qp[(size_t)ic*DIMF + tid] * 0.17677669529663687f;  // DH^-0.5
    __syncthreads();

    #pragma unroll
    for (int f = tid; f < KNB * (DIMF/4); f += 128) {
        int s = f >> 5, c4 = f & 31;
        *reinterpret_cast<float4*>(&kv[s][c4*4]) =
            *reinterpret_cast<const float4*>(&g_Kp[(size_t)nbr_s[s]*DIMF + c4*4]);
    }
    __syncthreads();

    const int h = tid >> 5, lane = tid & 31;
    const int cnt = s_cnt;
    float logit = -1e9f;
    if (lane < cnt) {
        float a = 0.f;
        #pragma unroll
        for (int d = 0; d < DH; d++) a += q[h*DH + d] * kv[lane][h*DH + d];
        logit = a;
    }
    float mx = logit;
    #pragma unroll
    for (int o = 16; o > 0; o >>= 1) mx = fmaxf(mx, __shfl_xor_sync(0xffffffffu, mx, o));
    float e = (lane < cnt) ? expf(logit - mx) : 0.f;
    float sm = e;
    #pragma unroll
    for (int o = 16; o > 0; o >>= 1) sm += __shfl_xor_sync(0xffffffffu, sm, o);
    at[h][lane] = e / sm;
    __syncthreads();

    #pragma unroll
    for (int f = tid; f < KNB * (DIMF/4); f += 128) {
        int s = f >> 5, c4 = f & 31;
        *reinterpret_cast<float4*>(&kv[s][c4*4]) =
            *reinterpret_cast<const float4*>(&g_Vp[(size_t)nbr_s[s]*DIMF + c4*4]);
    }
    __syncthreads();

    float acc = 0.f;
    #pragma unroll
    for (int kk = 0; kk < KNB; kk++) acc += at[h][kk] * kv[kk][h*DH + lane];
    g_ao[(size_t)m*DIMF + lane*NH + h] = acc;   // transpose(0,2,1) layout
}

// ---------------- LayerNorm + residual ----------------
__global__ void k_ln_res(const float* __restrict__ x,
                         const float* __restrict__ resid,
                         const float* __restrict__ g,
                         const float* __restrict__ b,
                         float* __restrict__ out,
                         int gatherResid)
{
    const int m = blockIdx.x, tid = threadIdx.x;
    __shared__ float red[4];
    float v = x[(size_t)m*DIMF + tid];
    float s = v;
    #pragma unroll
    for (int o = 16; o > 0; o >>= 1) s += __shfl_xor_sync(0xffffffffu, s, o);
    if ((tid & 31) == 0) red[tid >> 5] = s;
    __syncthreads();
    float mu = (red[0] + red[1] + red[2] + red[3]) * (1.f/DIMF);
    __syncthreads();
    float dv = v - mu;
    float s2 = dv * dv;
    #pragma unroll
    for (int o = 16; o > 0; o >>= 1) s2 += __shfl_xor_sync(0xffffffffu, s2, o);
    if ((tid & 31) == 0) red[tid >> 5] = s2;
    __syncthreads();
    float var = (red[0] + red[1] + red[2] + red[3]) * (1.f/DIMF);
    float ln = dv * rsqrtf(var + 1e-5f) * g[tid] + b[tid];
    int rrow = gatherResid ? g_idxc[m] : m;
    out[(size_t)m*DIMF + tid] = resid[(size_t)rrow*DIMF + tid] + ln;
}

// ---------------- final scatter: out = feats + c2[nearest] ----------------
__global__ void k_scatter(const float* __restrict__ feats, float* __restrict__ out) {
    int i = blockIdx.x * 256 + threadIdx.x;   // float4 index
    int n = i >> 5, c4 = i & 31;
    int ctr = (int)(g_nearKey[n] & 0xffffffffu);
    float4 f = *reinterpret_cast<const float4*>(feats + (size_t)n*DIMF + c4*4);
    float4 c = *reinterpret_cast<const float4*>(g_c2 + (size_t)ctr*DIMF + c4*4);
    f.x += c.x; f.y += c.y; f.z += c.z; f.w += c.w;
    *reinterpret_cast<float4*>(out + (size_t)n*DIMF + c4*4) = f;
}

// ---------------- launch (forked-stream graph) ----------------
extern "C" void kernel_launch(void* const* d_in, const int* in_sizes, int n_in,
                              void* d_out, int out_size) {
    const float* xyz   = (const float*)d_in[0];
    const float* feats = (const float*)d_in[1];
    const long long* idxc = (const long long*)d_in[2];
    const float* Wq = (const float*)d_in[3];
    const float* Wk = (const float*)d_in[4];
    const float* Wv = (const float*)d_in[5];
    const float* Wo = (const float*)d_in[6];
    const float* bo = (const float*)d_in[7];
    const float* g1 = (const float*)d_in[8];
    const float* be1 = (const float*)d_in[9];
    const float* g2 = (const float*)d_in[10];
    const float* be2 = (const float*)d_in[11];
    const float* W1 = (const float*)d_in[12];
    const float* b1f = (const float*)d_in[13];
    const float* W2 = (const float*)d_in[14];
    const float* b2f = (const float*)d_in[15];
    float* out = (float*)d_out;

    float *qp, *kp, *vp, *ao, *upd, *c1, *hid, *ffn, *c2;
    cudaGetSymbolAddress((void**)&qp,  g_Qp);
    cudaGetSymbolAddress((void**)&kp,  g_Kp);
    cudaGetSymbolAddress((void**)&vp,  g_Vp);
    cudaGetSymbolAddress((void**)&ao,  g_ao);
    cudaGetSymbolAddress((void**)&upd, g_upd);
    cudaGetSymbolAddress((void**)&c1,  g_c1);
    cudaGetSymbolAddress((void**)&hid, g_hid);
    cudaGetSymbolAddress((void**)&ffn, g_ffn);
    cudaGetSymbolAddress((void**)&c2,  g_c2);

    static cudaStream_t s1 = nullptr, s2 = nullptr;
    static cudaEvent_t eFork = nullptr, eTopk = nullptr, eNear = nullptr;
    if (!s1) {
        cudaStreamCreateWithFlags(&s1, cudaStreamNonBlocking);
        cudaStreamCreateWithFlags(&s2, cudaStreamNonBlocking);
        cudaEventCreateWithFlags(&eFork, cudaEventDisableTiming);
        cudaEventCreateWithFlags(&eTopk, cudaEventDisableTiming);
        cudaEventCreateWithFlags(&eNear, cudaEventDisableTiming);
    }
    cudaStream_t s0 = 0;

    k_cvt_idx<<<1, 256, 0, s0>>>(idxc);
    k_xx<<<NPTS/256, 256, 0, s0>>>(xyz);
    cudaEventRecord(eFork, s0);

    // fork: topk on s1, nearest on s2, QKV GEMM stays on s0
    cudaStreamWaitEvent(s1, eFork, 0);
    cudaStreamWaitEvent(s2, eFork, 0);
    k_topk<<<MC/CPB, 256, 0, s1>>>();
    cudaEventRecord(eTopk, s1);
    k_nearest<<<dim3(NPTS/512, MC/CCH), 256, 0, s2>>>();
    cudaEventRecord(eNear, s2);

    P3 p;
    p.W[0] = Wq; p.W[1] = Wk; p.W[2] = Wv;
    p.C[0] = qp; p.C[1] = kp; p.C[2] = vp;
    k_gemm_qkv<<<dim3(NPTS/128, 1, 3), 256, 0, s0>>>(feats, p);

    cudaStreamWaitEvent(s0, eTopk, 0);
    k_attn<<<MC, 128, 0, s0>>>();

    k_gemm<64,64><<<dim3(MC/64, DIMF/64), 256, 0, s0>>>(ao, Wo, bo, upd, DIMF, DIMF, 0);
    k_ln_res<<<MC, DIMF, 0, s0>>>(upd, feats, g1, be1, c1, 1);
    k_gemm<64,128><<<dim3(MC/64, HID/128), 256, 0, s0>>>(c1, W1, b1f, hid, DIMF, HID, 1);
    k_gemm<64,64><<<dim3(MC/64, DIMF/64), 256, 0, s0>>>(hid, W2, b2f, ffn, HID, DIMF, 0);
    k_ln_res<<<MC, DIMF, 0, s0>>>(ffn, c1, g2, be2, c2, 0);

    cudaStreamWaitEvent(s0, eNear, 0);
    k_scatter<<<NPTS*(DIMF/4)/256, 256, 0, s0>>>(feats, out);
}

// round 4
// speedup vs baseline: 1.9404x; 1.2716x over previous
#include <cuda_runtime.h>
#include <math.h>
#include <stdint.h>

#define NPTS 16384
#define MC   4096
#define DIMF 128
#define NH   4
#define DH   32
#define KNB  32
#define HID  512
#define RAD  0.3f
#define R2L  0.09000902f   // (RAD^2)*(1+1e-4): loose prefilter, exact test after
#define CAP  512
#define CPB  8
#define CCH  512   // centers per k_nearest block

// ---------------- scratch (device globals; no allocation) ----------------
__device__ int    g_idxc[MC];
__device__ float4 g_pts[NPTS];        // x,y,z,|x|^2
__device__ __align__(16) float g_Qp[NPTS*DIMF];
__device__ __align__(16) float g_Kp[NPTS*DIMF];
__device__ __align__(16) float g_Vp[NPTS*DIMF];
__device__ int    g_nbr[MC*KNB];
__device__ int    g_cnt[MC];
__device__ unsigned long long g_nearKey[NPTS];
__device__ __align__(16) float g_ao[MC*DIMF];
__device__ __align__(16) float g_upd[MC*DIMF];
__device__ __align__(16) float g_c1[MC*DIMF];
__device__ __align__(16) float g_hid[MC*HID];
__device__ __align__(16) float g_ffn[MC*DIMF];
__device__ __align__(16) float g_c2[MC*DIMF];

// ---------------- idx_center dtype detection + convert ----------------
__global__ void k_cvt_idx(const long long* __restrict__ raw) {
    __shared__ int s_ok;
    if (threadIdx.x == 0) s_ok = 1;
    __syncthreads();
    for (int m = threadIdx.x; m < MC/2; m += 256) {
        long long v = raw[m];
        if (v < 0 || v >= NPTS) s_ok = 0;
    }
    __syncthreads();
    if (s_ok) {
        for (int m = threadIdx.x; m < MC; m += 256)
            g_idxc[m] = (int)raw[m];
    } else {
        const int* r32 = (const int*)raw;
        for (int m = threadIdx.x; m < MC; m += 256)
            g_idxc[m] = r32[m];
    }
}

// pack points + init nearest keys
__global__ void k_xx(const float* __restrict__ xyz) {
    int n = blockIdx.x * 256 + threadIdx.x;
    float x = xyz[3*n], y = xyz[3*n+1], z = xyz[3*n+2];
    g_pts[n] = make_float4(x, y, z, x*x + y*y + z*z);
    g_nearKey[n] = ~0ull;
}

// ---------------- per-center radius filter + exact top-K by rank ----------------
__global__ __launch_bounds__(256) void k_topk() {
    __shared__ float cd[CPB][CAP];
    __shared__ int   ci[CPB][CAP];
    __shared__ int   s_cnt[CPB];
    const int tid = threadIdx.x;
    const int m0 = blockIdx.x * CPB;
    if (tid < CPB) s_cnt[tid] = 0;
    __syncthreads();

    float cx2[CPB], cy2[CPB], cz2[CPB], cc[CPB];
    #pragma unroll
    for (int g = 0; g < CPB; g++) {
        float4 c = g_pts[g_idxc[m0 + g]];
        cx2[g] = -2.f*c.x; cy2[g] = -2.f*c.y; cz2[g] = -2.f*c.z; cc[g] = c.w;
    }
    __syncthreads();

    for (int n = tid; n < NPTS; n += 256) {
        float4 p = g_pts[n];
        float rhs = R2L - p.w;
        #pragma unroll
        for (int g = 0; g < CPB; g++) {
            float t = fmaf(cx2[g], p.x, cc[g]);
            t = fmaf(cy2[g], p.y, t);
            t = fmaf(cz2[g], p.z, t);
            if (t < rhs) {
                float dist = sqrtf(fmaxf(t + p.w, 1e-12f));
                if (dist < RAD) {
                    int q = atomicAdd(&s_cnt[g], 1);
                    if (q < CAP) { cd[g][q] = dist; ci[g][q] = n; }
                }
            }
        }
    }
    __syncthreads();

    #pragma unroll
    for (int g = 0; g < CPB; g++) {
        int cnt = min(s_cnt[g], CAP);
        int m = m0 + g;
        for (int c = tid; c < cnt; c += 256) {
            float d = cd[g][c]; int i = ci[g][c];
            int rank = 0;
            for (int j = 0; j < cnt; j++) {
                float dj = cd[g][j];
                rank += (dj < d) || (dj == d && ci[g][j] < i);
            }
            if (rank < KNB) g_nbr[m*KNB + rank] = i;
        }
        int v = min(cnt, KNB);
        if (tid == 0) g_cnt[m] = v;
        if (tid >= v && tid < KNB) g_nbr[m*KNB + tid] = 0;
    }
}

// ---------------- per-point nearest center: 4 pts/thread + packed atomicMin ----
__global__ __launch_bounds__(256) void k_nearest() {
    __shared__ float4 sc[CCH];
    const int tid = threadIdx.x;
    const int nb = blockIdx.x * 1024 + tid;
    const int base = blockIdx.y * CCH;
    for (int j = tid; j < CCH; j += 256)
        sc[j] = g_pts[g_idxc[base + j]];
    float4 p0 = g_pts[nb], p1 = g_pts[nb+256], p2 = g_pts[nb+512], p3 = g_pts[nb+768];
    __syncthreads();
    float b0 = 3.4e38f, b1 = 3.4e38f, b2 = 3.4e38f, b3 = 3.4e38f;
    int i0 = 0, i1 = 0, i2 = 0, i3 = 0;
    #pragma unroll 4
    for (int j = 0; j < CCH; j++) {
        float4 c = sc[j];
        float d0 = fmaf(-2.f, fmaf(c.x, p0.x, fmaf(c.y, p0.y, c.z*p0.z)), c.w);
        float d1 = fmaf(-2.f, fmaf(c.x, p1.x, fmaf(c.y, p1.y, c.z*p1.z)), c.w);
        float d2 = fmaf(-2.f, fmaf(c.x, p2.x, fmaf(c.y, p2.y, c.z*p2.z)), c.w);
        float d3 = fmaf(-2.f, fmaf(c.x, p3.x, fmaf(c.y, p3.y, c.z*p3.z)), c.w);
        if (d0 < b0) { b0 = d0; i0 = j; }
        if (d1 < b1) { b1 = d1; i1 = j; }
        if (d2 < b2) { b2 = d2; i2 = j; }
        if (d3 < b3) { b3 = d3; i3 = j; }
    }
    unsigned long long k0 = ((unsigned long long)__float_as_uint(fmaxf(b0 + p0.w, 0.f)) << 32) | (unsigned)(base + i0);
    unsigned long long k1 = ((unsigned long long)__float_as_uint(fmaxf(b1 + p1.w, 0.f)) << 32) | (unsigned)(base + i1);
    unsigned long long k2 = ((unsigned long long)__float_as_uint(fmaxf(b2 + p2.w, 0.f)) << 32) | (unsigned)(base + i2);
    unsigned long long k3 = ((unsigned long long)__float_as_uint(fmaxf(b3 + p3.w, 0.f)) << 32) | (unsigned)(base + i3);
    atomicMin(&g_nearKey[nb],     k0);
    atomicMin(&g_nearKey[nb+256], k1);
    atomicMin(&g_nearKey[nb+512], k2);
    atomicMin(&g_nearKey[nb+768], k3);
}

// ---------------- TF32 tensor-core GEMM: C = A @ W^T (+bias)(+relu) ----------
__device__ __forceinline__ uint32_t cvt_tf32(float x) {
    uint32_t r;
    asm("cvt.rna.tf32.f32 %0, %1;" : "=r"(r) : "f"(x));
    return r;
}

template<int BM, int BN, int WM, int WN>
__device__ __forceinline__ void gemm_tf32_body(
    const float* __restrict__ A, const float* __restrict__ W,
    const float* __restrict__ bias, float* __restrict__ C,
    int Cin, int Cout, int relu)
{
    constexpr int BK = 32;
    constexpr int MT = WM / 16, NT = WN / 8;
    constexpr int WCOLS = BN / WN;
    __shared__ uint32_t As[BM][BK + 4];
    __shared__ uint32_t Ws[BN][BK + 4];

    const int tid = threadIdx.x;
    const int wid = tid >> 5, lane = tid & 31;
    const int wmBase = (wid / WCOLS) * WM;
    const int wnBase = (wid % WCOLS) * WN;
    const int rowBase = blockIdx.x * BM;
    const int colBase = blockIdx.y * BN;
    const int lr = lane >> 2, lc = lane & 3;

    float acc[MT][NT][4];
    #pragma unroll
    for (int i = 0; i < MT; i++)
        #pragma unroll
        for (int j = 0; j < NT; j++)
            #pragma unroll
            for (int q = 0; q < 4; q++) acc[i][j][q] = 0.f;

    for (int k0 = 0; k0 < Cin; k0 += BK) {
        #pragma unroll
        for (int f = tid; f < BM * (BK/4); f += 256) {
            int row = f >> 3, kq = f & 7;
            float4 v = *reinterpret_cast<const float4*>(A + (size_t)(rowBase + row)*Cin + k0 + kq*4);
            As[row][kq*4+0] = cvt_tf32(v.x); As[row][kq*4+1] = cvt_tf32(v.y);
            As[row][kq*4+2] = cvt_tf32(v.z); As[row][kq*4+3] = cvt_tf32(v.w);
        }
        #pragma unroll
        for (int f = tid; f < BN * (BK/4); f += 256) {
            int row = f >> 3, kq = f & 7;
            float4 v = *reinterpret_cast<const float4*>(W + (size_t)(colBase + row)*Cin + k0 + kq*4);
            Ws[row][kq*4+0] = cvt_tf32(v.x); Ws[row][kq*4+1] = cvt_tf32(v.y);
            Ws[row][kq*4+2] = cvt_tf32(v.z); Ws[row][kq*4+3] = cvt_tf32(v.w);
        }
        __syncthreads();

        #pragma unroll
        for (int ks = 0; ks < BK/8; ks++) {
            uint32_t bfr[NT][2];
            #pragma unroll
            for (int nt = 0; nt < NT; nt++) {
                int nn = wnBase + nt*8 + lr;
                bfr[nt][0] = Ws[nn][ks*8 + lc];
                bfr[nt][1] = Ws[nn][ks*8 + lc + 4];
            }
            uint32_t afr[MT][4];
            #pragma unroll
            for (int mt = 0; mt < MT; mt++) {
                int rr = wmBase + mt*16 + lr;
                afr[mt][0] = As[rr][ks*8 + lc];
                afr[mt][1] = As[rr + 8][ks*8 + lc];
                afr[mt][2] = As[rr][ks*8 + lc + 4];
                afr[mt][3] = As[rr + 8][ks*8 + lc + 4];
            }
            #pragma unroll
            for (int mt = 0; mt < MT; mt++)
                #pragma unroll
                for (int nt = 0; nt < NT; nt++) {
                    asm volatile(
                        "mma.sync.aligned.m16n8k8.row.col.f32.tf32.tf32.f32 "
                        "{%0,%1,%2,%3}, {%4,%5,%6,%7}, {%8,%9}, {%0,%1,%2,%3};\n"
                        : "+f"(acc[mt][nt][0]), "+f"(acc[mt][nt][1]),
                          "+f"(acc[mt][nt][2]), "+f"(acc[mt][nt][3])
                        : "r"(afr[mt][0]), "r"(afr[mt][1]), "r"(afr[mt][2]), "r"(afr[mt][3]),
                          "r"(bfr[nt][0]), "r"(bfr[nt][1]));
                }
        }
        __syncthreads();
    }

    #pragma unroll
    for (int mt = 0; mt < MT; mt++) {
        #pragma unroll
        for (int nt = 0; nt < NT; nt++) {
            int row0 = rowBase + wmBase + mt*16 + lr;
            int col  = colBase + wnBase + nt*8 + 2*lc;
            float bx = 0.f, by = 0.f;
            if (bias) { bx = bias[col]; by = bias[col+1]; }
            float2 o0 = make_float2(acc[mt][nt][0] + bx, acc[mt][nt][1] + by);
            float2 o1 = make_float2(acc[mt][nt][2] + bx, acc[mt][nt][3] + by);
            if (relu) {
                o0.x = fmaxf(o0.x, 0.f); o0.y = fmaxf(o0.y, 0.f);
                o1.x = fmaxf(o1.x, 0.f); o1.y = fmaxf(o1.y, 0.f);
            }
            *reinterpret_cast<float2*>(C + (size_t)row0*Cout + col) = o0;
            *reinterpret_cast<float2*>(C + (size_t)(row0+8)*Cout + col) = o1;
        }
    }
}

template<int BM, int BN, int WM, int WN>
__global__ __launch_bounds__(256, 2) void k_gemm_tf32(
    const float* __restrict__ A, const float* __restrict__ W,
    const float* __restrict__ bias, float* __restrict__ C,
    int Cin, int Cout, int relu)
{
    gemm_tf32_body<BM, BN, WM, WN>(A, W, bias, C, Cin, Cout, relu);
}

struct P3 { const float* W[3]; float* C[3]; };
__global__ __launch_bounds__(256, 2) void k_gemm_qkv(const float* __restrict__ A, P3 p)
{
    gemm_tf32_body<128, 128, 64, 32>(A, p.W[blockIdx.z], nullptr, p.C[blockIdx.z], DIMF, DIMF, 0);
}

// ---------------- per-center attention over K=32 neighbors ----------------
__global__ void k_attn() {
    __shared__ float q[DIMF];
    __shared__ float kv[KNB][DIMF + 4];
    __shared__ float at[NH][KNB];
    __shared__ int nbr_s[KNB];
    __shared__ int s_cnt;
    const int m = blockIdx.x, tid = threadIdx.x;
    if (tid < KNB) nbr_s[tid] = g_nbr[m*KNB + tid];
    if (tid == 0) s_cnt = g_cnt[m];
    int ic = g_idxc[m];
    q[tid] = g_Qp[(size_t)ic*DIMF + tid] * 0.17677669529663687f;  // DH^-0.5
    __syncthreads();

    #pragma unroll
    for (int f = tid; f < KNB * (DIMF/4); f += 128) {
        int s = f >> 5, c4 = f & 31;
        *reinterpret_cast<float4*>(&kv[s][c4*4]) =
            *reinterpret_cast<const float4*>(&g_Kp[(size_t)nbr_s[s]*DIMF + c4*4]);
    }
    __syncthreads();

    const int h = tid >> 5, lane = tid & 31;
    const int cnt = s_cnt;
    float logit = -1e9f;
    if (lane < cnt) {
        float a = 0.f;
        #pragma unroll
        for (int d = 0; d < DH; d++) a += q[h*DH + d] * kv[lane][h*DH + d];
        logit = a;
    }
    float mx = logit;
    #pragma unroll
    for (int o = 16; o > 0; o >>= 1) mx = fmaxf(mx, __shfl_xor_sync(0xffffffffu, mx, o));
    float e = (lane < cnt) ? expf(logit - mx) : 0.f;
    float sm = e;
    #pragma unroll
    for (int o = 16; o > 0; o >>= 1) sm += __shfl_xor_sync(0xffffffffu, sm, o);
    at[h][lane] = e / sm;
    __syncthreads();

    #pragma unroll
    for (int f = tid; f < KNB * (DIMF/4); f += 128) {
        int s = f >> 5, c4 = f & 31;
        *reinterpret_cast<float4*>(&kv[s][c4*4]) =
            *reinterpret_cast<const float4*>(&g_Vp[(size_t)nbr_s[s]*DIMF + c4*4]);
    }
    __syncthreads();

    float acc = 0.f;
    #pragma unroll
    for (int kk = 0; kk < KNB; kk++) acc += at[h][kk] * kv[kk][h*DH + lane];
    g_ao[(size_t)m*DIMF + lane*NH + h] = acc;   // transpose(0,2,1) layout
}

// ---------------- LayerNorm + residual ----------------
__global__ void k_ln_res(const float* __restrict__ x,
                         const float* __restrict__ resid,
                         const float* __restrict__ g,
                         const float* __restrict__ b,
                         float* __restrict__ out,
                         int gatherResid)
{
    const int m = blockIdx.x, tid = threadIdx.x;
    __shared__ float red[4];
    float v = x[(size_t)m*DIMF + tid];
    float s = v;
    #pragma unroll
    for (int o = 16; o > 0; o >>= 1) s += __shfl_xor_sync(0xffffffffu, s, o);
    if ((tid & 31) == 0) red[tid >> 5] = s;
    __syncthreads();
    float mu = (red[0] + red[1] + red[2] + red[3]) * (1.f/DIMF);
    __syncthreads();
    float dv = v - mu;
    float s2 = dv * dv;
    #pragma unroll
    for (int o = 16; o > 0; o >>= 1) s2 += __shfl_xor_sync(0xffffffffu, s2, o);
    if ((tid & 31) == 0) red[tid >> 5] = s2;
    __syncthreads();
    float var = (red[0] + red[1] + red[2] + red[3]) * (1.f/DIMF);
    float ln = dv * rsqrtf(var + 1e-5f) * g[tid] + b[tid];
    int rrow = gatherResid ? g_idxc[m] : m;
    out[(size_t)m*DIMF + tid] = resid[(size_t)rrow*DIMF + tid] + ln;
}

// ---------------- final scatter: out = feats + c2[nearest] ----------------
__global__ void k_scatter(const float* __restrict__ feats, float* __restrict__ out) {
    int i = blockIdx.x * 256 + threadIdx.x;   // float4 index
    int n = i >> 5, c4 = i & 31;
    int ctr = (int)(g_nearKey[n] & 0xffffffffu);
    float4 f = *reinterpret_cast<const float4*>(feats + (size_t)n*DIMF + c4*4);
    float4 c = *reinterpret_cast<const float4*>(g_c2 + (size_t)ctr*DIMF + c4*4);
    f.x += c.x; f.y += c.y; f.z += c.z; f.w += c.w;
    *reinterpret_cast<float4*>(out + (size_t)n*DIMF + c4*4) = f;
}

// ---------------- launch (forked-stream graph) ----------------
extern "C" void kernel_launch(void* const* d_in, const int* in_sizes, int n_in,
                              void* d_out, int out_size) {
    const float* xyz   = (const float*)d_in[0];
    const float* feats = (const float*)d_in[1];
    const long long* idxc = (const long long*)d_in[2];
    const float* Wq = (const float*)d_in[3];
    const float* Wk = (const float*)d_in[4];
    const float* Wv = (const float*)d_in[5];
    const float* Wo = (const float*)d_in[6];
    const float* bo = (const float*)d_in[7];
    const float* g1 = (const float*)d_in[8];
    const float* be1 = (const float*)d_in[9];
    const float* g2 = (const float*)d_in[10];
    const float* be2 = (const float*)d_in[11];
    const float* W1 = (const float*)d_in[12];
    const float* b1f = (const float*)d_in[13];
    const float* W2 = (const float*)d_in[14];
    const float* b2f = (const float*)d_in[15];
    float* out = (float*)d_out;

    float *qp, *kp, *vp, *ao, *upd, *c1, *hid, *ffn, *c2;
    cudaGetSymbolAddress((void**)&qp,  g_Qp);
    cudaGetSymbolAddress((void**)&kp,  g_Kp);
    cudaGetSymbolAddress((void**)&vp,  g_Vp);
    cudaGetSymbolAddress((void**)&ao,  g_ao);
    cudaGetSymbolAddress((void**)&upd, g_upd);
    cudaGetSymbolAddress((void**)&c1,  g_c1);
    cudaGetSymbolAddress((void**)&hid, g_hid);
    cudaGetSymbolAddress((void**)&ffn, g_ffn);
    cudaGetSymbolAddress((void**)&c2,  g_c2);

    static cudaStream_t s1 = nullptr, s2 = nullptr;
    static cudaEvent_t eFork = nullptr, eTopk = nullptr, eNear = nullptr;
    if (!s1) {
        cudaStreamCreateWithFlags(&s1, cudaStreamNonBlocking);
        cudaStreamCreateWithFlags(&s2, cudaStreamNonBlocking);
        cudaEventCreateWithFlags(&eFork, cudaEventDisableTiming);
        cudaEventCreateWithFlags(&eTopk, cudaEventDisableTiming);
        cudaEventCreateWithFlags(&eNear, cudaEventDisableTiming);
    }
    cudaStream_t s0 = 0;

    k_cvt_idx<<<1, 256, 0, s0>>>(idxc);
    k_xx<<<NPTS/256, 256, 0, s0>>>(xyz);
    cudaEventRecord(eFork, s0);

    cudaStreamWaitEvent(s1, eFork, 0);
    cudaStreamWaitEvent(s2, eFork, 0);
    k_topk<<<MC/CPB, 256, 0, s1>>>();
    cudaEventRecord(eTopk, s1);
    k_nearest<<<dim3(NPTS/1024, MC/CCH), 256, 0, s2>>>();
    cudaEventRecord(eNear, s2);

    P3 p;
    p.W[0] = Wq; p.W[1] = Wk; p.W[2] = Wv;
    p.C[0] = qp; p.C[1] = kp; p.C[2] = vp;
    k_gemm_qkv<<<dim3(NPTS/128, 1, 3), 256, 0, s0>>>(feats, p);

    cudaStreamWaitEvent(s0, eTopk, 0);
    k_attn<<<MC, 128, 0, s0>>>();

    k_gemm_tf32<64,64,32,16><<<dim3(MC/64, DIMF/64), 256, 0, s0>>>(ao, Wo, bo, upd, DIMF, DIMF, 0);
    k_ln_res<<<MC, DIMF, 0, s0>>>(upd, feats, g1, be1, c1, 1);
    k_gemm_tf32<128,128,64,32><<<dim3(MC/128, HID/128), 256, 0, s0>>>(c1, W1, b1f, hid, DIMF, HID, 1);
    k_gemm_tf32<64,64,32,16><<<dim3(MC/64, DIMF/64), 256, 0, s0>>>(hid, W2, b2f, ffn, HID, DIMF, 0);
    k_ln_res<<<MC, DIMF, 0, s0>>>(ffn, c1, g2, be2, c2, 0);

    cudaStreamWaitEvent(s0, eNear, 0);
    k_scatter<<<NPTS*(DIMF/4)/256, 256, 0, s0>>>(feats, out);
}